// round 5
// baseline (speedup 1.0000x reference)
#include <cuda_runtime.h>
#include <cuda_bf16.h>

// Problem constants (fixed by the reference setup)
constexpr int N_NODES = 50000;
constexpr int N_EDGES = 800000;
constexpr int NZ = N_NODES * 32;
constexpr int SCAN_B = 256;
constexpr int NB = (N_NODES + SCAN_B - 1) / SCAN_B;   // 196 scan blocks

// Scratch (device globals; referenced ONLY from device code — host-side
// references to __device__ symbols pass the host shadow address on GB300/ATS).
__device__ __align__(16) float g_dinv[N_NODES];
__device__ __align__(16) float g_ys32[N_NODES * 32];   // dinv * x
__device__ __align__(16) float g_bufA[N_NODES * 64];   // dinv * h1
__device__ __align__(16) float g_bufB[N_NODES * 64];   // dinv * h2
__device__ int g_cnt[N_NODES];          // histogram, then fill-cursor
__device__ int g_row[N_NODES + 1];      // CSR row offsets (by dst)
__device__ int g_srcs[N_EDGES];         // src ids sorted by dst
__device__ int g_bsum[NB];              // per-block count sums
__device__ int g_bpre[NB];              // exclusive prefix of block sums
__device__ int g_is64;

// ---------------------------------------------------------------------------
__device__ __forceinline__ int edge_idx(const void* p, int pos) {
    if (g_is64) return (int)((const long long*)p)[pos];
    return ((const int*)p)[pos];
}

// Detect int64 vs int32 edge_index + zero the histogram (fused).
__global__ void detect_zero_kernel(const void* ei) {
    int i = blockIdx.x * blockDim.x + threadIdx.x;
    if (i < N_NODES) g_cnt[i] = 0;
    if (i == 0) {
        const long long* p = (const long long*)ei;
        int ok = 1;
        for (int k = 0; k < 256; k++) {
            long long v = p[k];
            if (v < 0 || v >= N_NODES) { ok = 0; break; }
        }
        g_is64 = ok;
    }
}

// Histogram of dst
__global__ void hist_kernel(const void* ei) {
    int e = blockIdx.x * blockDim.x + threadIdx.x;
    if (e < N_EDGES) atomicAdd(&g_cnt[edge_idx(ei, N_EDGES + e)], 1);
}

// --- Two-level parallel exclusive scan of g_cnt -> g_row -----------------

__global__ void partial_kernel() {
    __shared__ int sh[SCAN_B];
    int i = blockIdx.x * SCAN_B + threadIdx.x;
    int v = (i < N_NODES) ? g_cnt[i] : 0;
    sh[threadIdx.x] = v;
    __syncthreads();
#pragma unroll
    for (int off = SCAN_B / 2; off > 0; off >>= 1) {
        if (threadIdx.x < off) sh[threadIdx.x] += sh[threadIdx.x + off];
        __syncthreads();
    }
    if (threadIdx.x == 0) g_bsum[blockIdx.x] = sh[0];
}

__global__ void scan_bsum_kernel() {
    __shared__ int sh[SCAN_B];
    int t = threadIdx.x;
    int v = (t < NB) ? g_bsum[t] : 0;
    sh[t] = v;
    __syncthreads();
#pragma unroll
    for (int off = 1; off < SCAN_B; off <<= 1) {
        int u = (t >= off) ? sh[t - off] : 0;
        __syncthreads();
        sh[t] += u;
        __syncthreads();
    }
    if (t < NB) g_bpre[t] = sh[t] - v;   // exclusive
}

__global__ void offsets_kernel() {
    __shared__ int sh[SCAN_B];
    int t = threadIdx.x;
    int i = blockIdx.x * SCAN_B + t;
    int c = (i < N_NODES) ? g_cnt[i] : 0;
    sh[t] = c;
    __syncthreads();
#pragma unroll
    for (int off = 1; off < SCAN_B; off <<= 1) {
        int u = (t >= off) ? sh[t - off] : 0;
        __syncthreads();
        sh[t] += u;
        __syncthreads();
    }
    if (i < N_NODES) {
        int r = g_bpre[blockIdx.x] + sh[t] - c;   // exclusive global prefix
        g_row[i] = r;
        g_cnt[i] = r;                              // fill cursor
        g_dinv[i] = rsqrtf((float)(c + 1));        // deg incl. self-loop
    }
    if (i == 0) g_row[N_NODES] = N_EDGES;
}

// Bucket fill: csr src list sorted by dst
__global__ void fill_kernel(const void* ei) {
    int e = blockIdx.x * blockDim.x + threadIdx.x;
    if (e < N_EDGES) {
        int s = edge_idx(ei, e);
        int d = edge_idx(ei, N_EDGES + e);
        int pos = atomicAdd(&g_cnt[d], 1);
        g_srcs[pos] = s;
    }
}

// ys32 = dinv ⊙ x  (float4 lanes)
__global__ void scale0_kernel(const float* __restrict__ x) {
    int i = blockIdx.x * blockDim.x + threadIdx.x;
    if (i < N_NODES * 8) {
        float4 v = ((const float4*)x)[i];
        float dv = g_dinv[i >> 3];
        ((float4*)g_ys32)[i] = make_float4(dv * v.x, dv * v.y, dv * v.z, dv * v.w);
    }
}

// ---------------------------------------------------------------------------
// Fused pull + GEMM kernels. Block = 256 threads = 8 warps; one warp per node.
// Edge loop unrolled x8: 8 independent index loads then 8 independent gathers
// in flight (MLP ~8) to cover the ~250-cycle L2 hit latency.
// ---------------------------------------------------------------------------

// Layer 1: a[32] = dinv*(Σ ys32[src] + ys32[n]); bufA = dinv*relu(a@W1 + b1)
__global__ void __launch_bounds__(256) pull1_kernel(
    const float* __restrict__ W1, const float* __restrict__ b1) {
    __shared__ float sW[32 * 64];
    __shared__ float sb[64];
    __shared__ float4 sa[8][8];   // 8 warps x 32 floats
    int tid = threadIdx.x;
    for (int i = tid; i < 32 * 64; i += 256) sW[i] = W1[i];
    if (tid < 64) sb[tid] = b1[tid];
    __syncthreads();

    int w = tid >> 5, lane = tid & 31;
    for (int n = blockIdx.x * 8 + w; n < N_NODES; n += gridDim.x * 8) {
        float acc = g_ys32[n * 32 + lane];
        int e = g_row[n], end = g_row[n + 1];
        for (; e + 8 <= end; e += 8) {
            int s0 = g_srcs[e + 0], s1 = g_srcs[e + 1];
            int s2 = g_srcs[e + 2], s3 = g_srcs[e + 3];
            int s4 = g_srcs[e + 4], s5 = g_srcs[e + 5];
            int s6 = g_srcs[e + 6], s7 = g_srcs[e + 7];
            float v0 = g_ys32[s0 * 32 + lane], v1 = g_ys32[s1 * 32 + lane];
            float v2 = g_ys32[s2 * 32 + lane], v3 = g_ys32[s3 * 32 + lane];
            float v4 = g_ys32[s4 * 32 + lane], v5 = g_ys32[s5 * 32 + lane];
            float v6 = g_ys32[s6 * 32 + lane], v7 = g_ys32[s7 * 32 + lane];
            acc += ((v0 + v1) + (v2 + v3)) + ((v4 + v5) + (v6 + v7));
        }
        for (; e < end; e++) acc += g_ys32[g_srcs[e] * 32 + lane];
        float dv = g_dinv[n];
        ((float*)sa[w])[lane] = dv * acc;
        __syncwarp();
        // GEMM: this lane computes outputs 2*lane, 2*lane+1
        float s0 = sb[2 * lane], s1 = sb[2 * lane + 1];
#pragma unroll
        for (int k4 = 0; k4 < 8; k4++) {
            float4 a = sa[w][k4];
            float2 r0 = *(const float2*)&sW[(4 * k4 + 0) * 64 + 2 * lane];
            float2 r1 = *(const float2*)&sW[(4 * k4 + 1) * 64 + 2 * lane];
            float2 r2 = *(const float2*)&sW[(4 * k4 + 2) * 64 + 2 * lane];
            float2 r3 = *(const float2*)&sW[(4 * k4 + 3) * 64 + 2 * lane];
            s0 = fmaf(a.x, r0.x, s0); s1 = fmaf(a.x, r0.y, s1);
            s0 = fmaf(a.y, r1.x, s0); s1 = fmaf(a.y, r1.y, s1);
            s0 = fmaf(a.z, r2.x, s0); s1 = fmaf(a.z, r2.y, s1);
            s0 = fmaf(a.w, r3.x, s0); s1 = fmaf(a.w, r3.y, s1);
        }
        float2 o = make_float2(dv * fmaxf(s0, 0.f), dv * fmaxf(s1, 0.f));
        ((float2*)g_bufA)[n * 32 + lane] = o;
        __syncwarp();   // everyone done with sa[w] before next iteration
    }
}

// 64-dim pull (float2 per lane) with x8 unroll; returns scaled acc in sa.
__device__ __forceinline__ float2 pull64(const float2* __restrict__ in2,
                                         int n, int lane) {
    float2 acc = in2[n * 32 + lane];
    int e = g_row[n], end = g_row[n + 1];
    for (; e + 8 <= end; e += 8) {
        int s0 = g_srcs[e + 0], s1 = g_srcs[e + 1];
        int s2 = g_srcs[e + 2], s3 = g_srcs[e + 3];
        int s4 = g_srcs[e + 4], s5 = g_srcs[e + 5];
        int s6 = g_srcs[e + 6], s7 = g_srcs[e + 7];
        float2 v0 = in2[s0 * 32 + lane], v1 = in2[s1 * 32 + lane];
        float2 v2 = in2[s2 * 32 + lane], v3 = in2[s3 * 32 + lane];
        float2 v4 = in2[s4 * 32 + lane], v5 = in2[s5 * 32 + lane];
        float2 v6 = in2[s6 * 32 + lane], v7 = in2[s7 * 32 + lane];
        acc.x += ((v0.x + v1.x) + (v2.x + v3.x)) + ((v4.x + v5.x) + (v6.x + v7.x));
        acc.y += ((v0.y + v1.y) + (v2.y + v3.y)) + ((v4.y + v5.y) + (v6.y + v7.y));
    }
    for (; e < end; e++) {
        float2 v = in2[g_srcs[e] * 32 + lane];
        acc.x += v.x; acc.y += v.y;
    }
    return acc;
}

// Layer 2: pull 64-dim from bufA, GEMM 64x64, bufB = dinv*relu(.)
__global__ void __launch_bounds__(256) pull2_kernel(
    const float* __restrict__ W2, const float* __restrict__ b2) {
    __shared__ float sW[64 * 64];
    __shared__ float sb[64];
    __shared__ float4 sa[8][16];  // 8 warps x 64 floats
    int tid = threadIdx.x;
    for (int i = tid; i < 64 * 64; i += 256) sW[i] = W2[i];
    if (tid < 64) sb[tid] = b2[tid];
    __syncthreads();

    int w = tid >> 5, lane = tid & 31;
    const float2* in2 = (const float2*)g_bufA;
    for (int n = blockIdx.x * 8 + w; n < N_NODES; n += gridDim.x * 8) {
        float2 acc = pull64(in2, n, lane);
        float dv = g_dinv[n];
        ((float2*)sa[w])[lane] = make_float2(dv * acc.x, dv * acc.y);
        __syncwarp();
        float s0 = sb[2 * lane], s1 = sb[2 * lane + 1];
#pragma unroll
        for (int k4 = 0; k4 < 16; k4++) {
            float4 a = sa[w][k4];
            float2 r0 = *(const float2*)&sW[(4 * k4 + 0) * 64 + 2 * lane];
            float2 r1 = *(const float2*)&sW[(4 * k4 + 1) * 64 + 2 * lane];
            float2 r2 = *(const float2*)&sW[(4 * k4 + 2) * 64 + 2 * lane];
            float2 r3 = *(const float2*)&sW[(4 * k4 + 3) * 64 + 2 * lane];
            s0 = fmaf(a.x, r0.x, s0); s1 = fmaf(a.x, r0.y, s1);
            s0 = fmaf(a.y, r1.x, s0); s1 = fmaf(a.y, r1.y, s1);
            s0 = fmaf(a.z, r2.x, s0); s1 = fmaf(a.z, r2.y, s1);
            s0 = fmaf(a.w, r3.x, s0); s1 = fmaf(a.w, r3.y, s1);
        }
        float2 o = make_float2(dv * fmaxf(s0, 0.f), dv * fmaxf(s1, 0.f));
        ((float2*)g_bufB)[n * 32 + lane] = o;
        __syncwarp();
    }
}

// Heads: pull 64-dim from bufB (ONE aggregation for both heads),
// mu = a@W_mu+b_mu, lv = a@W_lv+b_lv, z = mu + exp(0.5 lv)*eps.
// Output layout: [z | mu | logvar].
__global__ void __launch_bounds__(256) pull3_kernel(
    const float* __restrict__ W_mu, const float* __restrict__ b_mu,
    const float* __restrict__ W_lv, const float* __restrict__ b_lv,
    const float* __restrict__ eps, float* __restrict__ out) {
    __shared__ float2 sWml[64 * 32];   // interleaved {Wmu, Wlv}
    __shared__ float sbm[32], sbl[32];
    __shared__ float4 sa[8][16];
    int tid = threadIdx.x;
    for (int i = tid; i < 64 * 32; i += 256)
        sWml[i] = make_float2(W_mu[i], W_lv[i]);
    if (tid < 32) { sbm[tid] = b_mu[tid]; sbl[tid] = b_lv[tid]; }
    __syncthreads();

    int w = tid >> 5, lane = tid & 31;
    const float2* in2 = (const float2*)g_bufB;
    for (int n = blockIdx.x * 8 + w; n < N_NODES; n += gridDim.x * 8) {
        float2 acc = pull64(in2, n, lane);
        float dv = g_dinv[n];
        ((float2*)sa[w])[lane] = make_float2(dv * acc.x, dv * acc.y);
        __syncwarp();
        float mu = sbm[lane], lv = sbl[lane];
#pragma unroll
        for (int k4 = 0; k4 < 16; k4++) {
            float4 a = sa[w][k4];
            float2 m0 = sWml[(4 * k4 + 0) * 32 + lane];
            float2 m1 = sWml[(4 * k4 + 1) * 32 + lane];
            float2 m2 = sWml[(4 * k4 + 2) * 32 + lane];
            float2 m3 = sWml[(4 * k4 + 3) * 32 + lane];
            mu = fmaf(a.x, m0.x, mu); lv = fmaf(a.x, m0.y, lv);
            mu = fmaf(a.y, m1.x, mu); lv = fmaf(a.y, m1.y, lv);
            mu = fmaf(a.z, m2.x, mu); lv = fmaf(a.z, m2.y, lv);
            mu = fmaf(a.w, m3.x, mu); lv = fmaf(a.w, m3.y, lv);
        }
        float z = fmaf(expf(0.5f * lv), eps[n * 32 + lane], mu);
        int o = n * 32 + lane;
        out[o] = z;
        out[NZ + o] = mu;
        out[2 * NZ + o] = lv;
        __syncwarp();
    }
}

// ---------------------------------------------------------------------------
extern "C" void kernel_launch(void* const* d_in, const int* in_sizes, int n_in,
                              void* d_out, int out_size) {
    const float* x    = (const float*)d_in[0];
    const void*  ei   = d_in[1];
    const float* W1   = (const float*)d_in[2];
    const float* b1   = (const float*)d_in[3];
    const float* W2   = (const float*)d_in[4];
    const float* b2   = (const float*)d_in[5];
    const float* W_mu = (const float*)d_in[6];
    const float* b_mu = (const float*)d_in[7];
    const float* W_lv = (const float*)d_in[8];
    const float* b_lv = (const float*)d_in[9];
    const float* eps  = (const float*)d_in[10];
    float* out = (float*)d_out;

    const int TB = 256;
    auto grid = [](long long n, int tb) { return (int)((n + tb - 1) / tb); };
    const int PG = 1184;   // persistent pull blocks (8/SM x 148)

    detect_zero_kernel<<<grid(N_NODES, TB), TB>>>(ei);
    hist_kernel<<<grid(N_EDGES, TB), TB>>>(ei);
    partial_kernel<<<NB, SCAN_B>>>();
    scan_bsum_kernel<<<1, SCAN_B>>>();
    offsets_kernel<<<NB, SCAN_B>>>();
    fill_kernel<<<grid(N_EDGES, TB), TB>>>(ei);
    scale0_kernel<<<grid(N_NODES * 8, TB), TB>>>(x);

    pull1_kernel<<<PG, 256>>>(W1, b1);
    pull2_kernel<<<PG, 256>>>(W2, b2);
    pull3_kernel<<<PG, 256>>>(W_mu, b_mu, W_lv, b_lv, eps, out);
}

// round 6
// speedup vs baseline: 1.0218x; 1.0218x over previous
#include <cuda_runtime.h>
#include <cuda_bf16.h>

// Problem constants (fixed by the reference setup)
constexpr int N_NODES = 50000;
constexpr int N_EDGES = 800000;
constexpr int NZ = N_NODES * 32;
constexpr int SCAN_B = 256;
constexpr int NB = (N_NODES + SCAN_B - 1) / SCAN_B;   // 196 scan blocks

// Scratch (device globals; referenced ONLY from device code — host-side
// references to __device__ symbols pass the host shadow address on GB300/ATS).
__device__ __align__(16) float g_dinv[N_NODES];
__device__ __align__(16) float g_ys32[N_NODES * 32];   // dinv * x
__device__ __align__(16) float g_bufA[N_NODES * 64];   // dinv * h1
__device__ __align__(16) float g_bufB[N_NODES * 64];   // dinv * h2
__device__ int g_cnt[N_NODES];          // histogram, then fill-cursor
__device__ int g_row[N_NODES + 1];      // CSR row offsets (by dst)
__device__ int g_srcs[N_EDGES];         // src ids sorted by dst
__device__ int g_state[NB];             // lookback scan state (flag|value)
__device__ int g_is64;

constexpr int FLAG_AGG = 1 << 30;
constexpr int FLAG_PRE = 2 << 30;
constexpr int VAL_MASK = (1 << 30) - 1;

// ---------------------------------------------------------------------------
__device__ __forceinline__ int edge_idx(const void* p, int pos) {
    if (g_is64) return (int)((const long long*)p)[pos];
    return ((const int*)p)[pos];
}

// Detect int64 vs int32 edge_index + zero histogram + zero scan state.
__global__ void detect_zero_kernel(const void* ei) {
    int i = blockIdx.x * blockDim.x + threadIdx.x;
    if (i < N_NODES) g_cnt[i] = 0;
    if (i < NB) g_state[i] = 0;       // replay-safe re-init
    if (i == 0) {
        const long long* p = (const long long*)ei;
        int ok = 1;
        for (int k = 0; k < 256; k++) {
            long long v = p[k];
            if (v < 0 || v >= N_NODES) { ok = 0; break; }
        }
        g_is64 = ok;
    }
}

// Histogram of dst
__global__ void hist_kernel(const void* ei) {
    int e = blockIdx.x * blockDim.x + threadIdx.x;
    if (e < N_EDGES) atomicAdd(&g_cnt[edge_idx(ei, N_EDGES + e)], 1);
}

// ---------------------------------------------------------------------------
// Single-pass scan (decoupled lookback) + dinv + fill-cursor + ys32 scaling.
// Block b handles nodes [b*256, b*256+256).
// ---------------------------------------------------------------------------
__global__ void __launch_bounds__(SCAN_B) scan_fused_kernel(
    const float* __restrict__ x) {
    __shared__ int sh[SCAN_B];
    __shared__ int s_base;
    __shared__ float sdv[SCAN_B];
    int t = threadIdx.x, b = blockIdx.x;
    int i = b * SCAN_B + t;
    int c = (i < N_NODES) ? g_cnt[i] : 0;

    // inclusive Hillis-Steele scan
    sh[t] = c;
    __syncthreads();
#pragma unroll
    for (int off = 1; off < SCAN_B; off <<= 1) {
        int u = (t >= off) ? sh[t - off] : 0;
        __syncthreads();
        sh[t] += u;
        __syncthreads();
    }
    int incl = sh[t];
    int blockTotal = sh[SCAN_B - 1];

    if (t == 0) {
        if (b == 0) {
            atomicExch(&g_state[0], blockTotal | FLAG_PRE);
            s_base = 0;
        } else {
            atomicExch(&g_state[b], blockTotal | FLAG_AGG);
            int base = 0;
            for (int j = b - 1; j >= 0; j--) {
                int v;
                do { v = atomicAdd(&g_state[j], 0); } while ((v & ~VAL_MASK) == 0);
                base += v & VAL_MASK;
                if (v & FLAG_PRE) break;
            }
            atomicExch(&g_state[b], (base + blockTotal) | FLAG_PRE);
            s_base = base;
        }
    }
    float dv = rsqrtf((float)(c + 1));   // deg incl. self-loop
    sdv[t] = dv;
    __syncthreads();

    int r = s_base + incl - c;           // exclusive global prefix
    if (i < N_NODES) {
        g_row[i] = r;
        g_cnt[i] = r;                     // fill cursor
        g_dinv[i] = dv;
    }
    if (i == 0) g_row[N_NODES] = N_EDGES;

    // fused scale0: ys32 = dinv * x for this block's 256 nodes (8 float4/node)
    const float4* x4 = (const float4*)x;
    float4* y4 = (float4*)g_ys32;
    int node0 = b * SCAN_B;
    for (int k = t; k < SCAN_B * 8; k += SCAN_B) {
        int ln = k >> 3;
        int node = node0 + ln;
        if (node < N_NODES) {
            float4 v = x4[node * 8 + (k & 7)];
            float d = sdv[ln];
            y4[node * 8 + (k & 7)] = make_float4(d * v.x, d * v.y, d * v.z, d * v.w);
        }
    }
}

// Bucket fill: csr src list sorted by dst
__global__ void fill_kernel(const void* ei) {
    int e = blockIdx.x * blockDim.x + threadIdx.x;
    if (e < N_EDGES) {
        int s = edge_idx(ei, e);
        int d = edge_idx(ei, N_EDGES + e);
        int pos = atomicAdd(&g_cnt[d], 1);
        g_srcs[pos] = s;
    }
}

// ---------------------------------------------------------------------------
// Fused pull + GEMM kernels. Block = 256 threads = 8 warps; one warp per node;
// grid-stride loop over node groups so W is loaded into shared once per block.
// Edge loop unrolled x2 (x8 hurt occupancy; TLP covers latency).
// ---------------------------------------------------------------------------

// Layer 1: a[32] = dinv*(Σ ys32[src] + ys32[n]); bufA = dinv*relu(a@W1 + b1)
__global__ void __launch_bounds__(256) pull1_kernel(
    const float* __restrict__ W1, const float* __restrict__ b1) {
    __shared__ float sW[32 * 64];
    __shared__ float sb[64];
    __shared__ float4 sa[8][8];   // 8 warps x 32 floats
    int tid = threadIdx.x;
    for (int i = tid; i < 32 * 64; i += 256) sW[i] = W1[i];
    if (tid < 64) sb[tid] = b1[tid];
    __syncthreads();

    int w = tid >> 5, lane = tid & 31;
    for (int n = blockIdx.x * 8 + w; n < N_NODES; n += gridDim.x * 8) {
        float acc = g_ys32[n * 32 + lane];
        int e = g_row[n], end = g_row[n + 1];
        for (; e + 1 < end; e += 2) {
            int s0 = g_srcs[e], s1 = g_srcs[e + 1];
            acc += g_ys32[s0 * 32 + lane] + g_ys32[s1 * 32 + lane];
        }
        if (e < end) acc += g_ys32[g_srcs[e] * 32 + lane];
        float dv = g_dinv[n];
        ((float*)sa[w])[lane] = dv * acc;
        __syncwarp();
        // GEMM: this lane computes outputs 2*lane, 2*lane+1
        float s0 = sb[2 * lane], s1 = sb[2 * lane + 1];
#pragma unroll
        for (int k4 = 0; k4 < 8; k4++) {
            float4 a = sa[w][k4];
            float2 r0 = *(const float2*)&sW[(4 * k4 + 0) * 64 + 2 * lane];
            float2 r1 = *(const float2*)&sW[(4 * k4 + 1) * 64 + 2 * lane];
            float2 r2 = *(const float2*)&sW[(4 * k4 + 2) * 64 + 2 * lane];
            float2 r3 = *(const float2*)&sW[(4 * k4 + 3) * 64 + 2 * lane];
            s0 = fmaf(a.x, r0.x, s0); s1 = fmaf(a.x, r0.y, s1);
            s0 = fmaf(a.y, r1.x, s0); s1 = fmaf(a.y, r1.y, s1);
            s0 = fmaf(a.z, r2.x, s0); s1 = fmaf(a.z, r2.y, s1);
            s0 = fmaf(a.w, r3.x, s0); s1 = fmaf(a.w, r3.y, s1);
        }
        float2 o = make_float2(dv * fmaxf(s0, 0.f), dv * fmaxf(s1, 0.f));
        ((float2*)g_bufA)[n * 32 + lane] = o;
        __syncwarp();   // everyone done with sa[w] before next iteration
    }
}

// Layer 2: pull 64-dim from bufA, GEMM 64x64, bufB = dinv*relu(.)
__global__ void __launch_bounds__(256) pull2_kernel(
    const float* __restrict__ W2, const float* __restrict__ b2) {
    __shared__ float sW[64 * 64];
    __shared__ float sb[64];
    __shared__ float4 sa[8][16];  // 8 warps x 64 floats
    int tid = threadIdx.x;
    for (int i = tid; i < 64 * 64; i += 256) sW[i] = W2[i];
    if (tid < 64) sb[tid] = b2[tid];
    __syncthreads();

    int w = tid >> 5, lane = tid & 31;
    const float2* in2 = (const float2*)g_bufA;
    for (int n = blockIdx.x * 8 + w; n < N_NODES; n += gridDim.x * 8) {
        float2 acc = in2[n * 32 + lane];
        int e = g_row[n], end = g_row[n + 1];
        for (; e + 1 < end; e += 2) {
            int s0 = g_srcs[e], s1 = g_srcs[e + 1];
            float2 v0 = in2[s0 * 32 + lane];
            float2 v1 = in2[s1 * 32 + lane];
            acc.x += v0.x + v1.x;
            acc.y += v0.y + v1.y;
        }
        if (e < end) {
            float2 v = in2[g_srcs[e] * 32 + lane];
            acc.x += v.x; acc.y += v.y;
        }
        float dv = g_dinv[n];
        ((float2*)sa[w])[lane] = make_float2(dv * acc.x, dv * acc.y);
        __syncwarp();
        float s0 = sb[2 * lane], s1 = sb[2 * lane + 1];
#pragma unroll
        for (int k4 = 0; k4 < 16; k4++) {
            float4 a = sa[w][k4];
            float2 r0 = *(const float2*)&sW[(4 * k4 + 0) * 64 + 2 * lane];
            float2 r1 = *(const float2*)&sW[(4 * k4 + 1) * 64 + 2 * lane];
            float2 r2 = *(const float2*)&sW[(4 * k4 + 2) * 64 + 2 * lane];
            float2 r3 = *(const float2*)&sW[(4 * k4 + 3) * 64 + 2 * lane];
            s0 = fmaf(a.x, r0.x, s0); s1 = fmaf(a.x, r0.y, s1);
            s0 = fmaf(a.y, r1.x, s0); s1 = fmaf(a.y, r1.y, s1);
            s0 = fmaf(a.z, r2.x, s0); s1 = fmaf(a.z, r2.y, s1);
            s0 = fmaf(a.w, r3.x, s0); s1 = fmaf(a.w, r3.y, s1);
        }
        float2 o = make_float2(dv * fmaxf(s0, 0.f), dv * fmaxf(s1, 0.f));
        ((float2*)g_bufB)[n * 32 + lane] = o;
        __syncwarp();
    }
}

// Heads: pull 64-dim from bufB (ONE aggregation for both heads),
// mu = a@W_mu+b_mu, lv = a@W_lv+b_lv, z = mu + exp(0.5 lv)*eps.
// Output layout: [z | mu | logvar].
__global__ void __launch_bounds__(256) pull3_kernel(
    const float* __restrict__ W_mu, const float* __restrict__ b_mu,
    const float* __restrict__ W_lv, const float* __restrict__ b_lv,
    const float* __restrict__ eps, float* __restrict__ out) {
    __shared__ float2 sWml[64 * 32];   // interleaved {Wmu, Wlv}
    __shared__ float sbm[32], sbl[32];
    __shared__ float4 sa[8][16];
    int tid = threadIdx.x;
    for (int i = tid; i < 64 * 32; i += 256)
        sWml[i] = make_float2(W_mu[i], W_lv[i]);
    if (tid < 32) { sbm[tid] = b_mu[tid]; sbl[tid] = b_lv[tid]; }
    __syncthreads();

    int w = tid >> 5, lane = tid & 31;
    const float2* in2 = (const float2*)g_bufB;
    for (int n = blockIdx.x * 8 + w; n < N_NODES; n += gridDim.x * 8) {
        float2 acc = in2[n * 32 + lane];
        int e = g_row[n], end = g_row[n + 1];
        for (; e + 1 < end; e += 2) {
            int s0 = g_srcs[e], s1 = g_srcs[e + 1];
            float2 v0 = in2[s0 * 32 + lane];
            float2 v1 = in2[s1 * 32 + lane];
            acc.x += v0.x + v1.x;
            acc.y += v0.y + v1.y;
        }
        if (e < end) {
            float2 v = in2[g_srcs[e] * 32 + lane];
            acc.x += v.x; acc.y += v.y;
        }
        float dv = g_dinv[n];
        ((float2*)sa[w])[lane] = make_float2(dv * acc.x, dv * acc.y);
        __syncwarp();
        float mu = sbm[lane], lv = sbl[lane];
#pragma unroll
        for (int k4 = 0; k4 < 16; k4++) {
            float4 a = sa[w][k4];
            float2 m0 = sWml[(4 * k4 + 0) * 32 + lane];
            float2 m1 = sWml[(4 * k4 + 1) * 32 + lane];
            float2 m2 = sWml[(4 * k4 + 2) * 32 + lane];
            float2 m3 = sWml[(4 * k4 + 3) * 32 + lane];
            mu = fmaf(a.x, m0.x, mu); lv = fmaf(a.x, m0.y, lv);
            mu = fmaf(a.y, m1.x, mu); lv = fmaf(a.y, m1.y, lv);
            mu = fmaf(a.z, m2.x, mu); lv = fmaf(a.z, m2.y, lv);
            mu = fmaf(a.w, m3.x, mu); lv = fmaf(a.w, m3.y, lv);
        }
        float z = fmaf(expf(0.5f * lv), eps[n * 32 + lane], mu);
        int o = n * 32 + lane;
        out[o] = z;
        out[NZ + o] = mu;
        out[2 * NZ + o] = lv;
        __syncwarp();
    }
}

// ---------------------------------------------------------------------------
extern "C" void kernel_launch(void* const* d_in, const int* in_sizes, int n_in,
                              void* d_out, int out_size) {
    const float* x    = (const float*)d_in[0];
    const void*  ei   = d_in[1];
    const float* W1   = (const float*)d_in[2];
    const float* b1   = (const float*)d_in[3];
    const float* W2   = (const float*)d_in[4];
    const float* b2   = (const float*)d_in[5];
    const float* W_mu = (const float*)d_in[6];
    const float* b_mu = (const float*)d_in[7];
    const float* W_lv = (const float*)d_in[8];
    const float* b_lv = (const float*)d_in[9];
    const float* eps  = (const float*)d_in[10];
    float* out = (float*)d_out;

    const int TB = 256;
    auto grid = [](long long n, int tb) { return (int)((n + tb - 1) / tb); };
    const int PG = 1184;   // persistent pull blocks (8/SM x 148)

    detect_zero_kernel<<<grid(N_NODES, TB), TB>>>(ei);
    hist_kernel<<<grid(N_EDGES, TB), TB>>>(ei);
    scan_fused_kernel<<<NB, SCAN_B>>>(x);     // scan + dinv + cursor + scale0
    fill_kernel<<<grid(N_EDGES, TB), TB>>>(ei);

    pull1_kernel<<<PG, 256>>>(W1, b1);
    pull2_kernel<<<PG, 256>>>(W2, b2);
    pull3_kernel<<<PG, 256>>>(W_mu, b_mu, W_lv, b_lv, eps, out);
}

// round 7
// speedup vs baseline: 1.0723x; 1.0494x over previous
#include <cuda_runtime.h>
#include <cuda_bf16.h>

// Problem constants (fixed by the reference setup)
constexpr int N_NODES = 50000;
constexpr int N_EDGES = 800000;
constexpr int NZ = N_NODES * 32;
constexpr int SCAN_B = 256;
constexpr int NB = (N_NODES + SCAN_B - 1) / SCAN_B;   // 196 scan blocks

// Scratch (device globals; referenced ONLY from device code — host-side
// references to __device__ symbols pass the host shadow address on GB300/ATS).
__device__ __align__(16) float g_dinv[N_NODES];
__device__ __align__(16) float g_ys32[N_NODES * 32];   // dinv * x
__device__ __align__(16) float g_bufA[N_NODES * 64];   // dinv * h1
__device__ __align__(16) float g_bufB[N_NODES * 64];   // dinv * h2
__device__ int g_cnt[N_NODES];          // histogram, then fill-cursor
__device__ int g_row[N_NODES + 1];      // CSR row offsets (by dst)
__device__ int g_srcs[N_EDGES];         // src ids sorted by dst
__device__ int g_state[NB];             // lookback scan state (flag|value)
__device__ int g_is64;

constexpr int FLAG_AGG = 1 << 30;
constexpr int FLAG_PRE = 2 << 30;
constexpr int VAL_MASK = (1 << 30) - 1;

// ---------------------------------------------------------------------------
__device__ __forceinline__ int edge_idx(const void* p, int pos, int is64) {
    if (is64) return (int)((const long long*)p)[pos];
    return ((const int*)p)[pos];
}

// Detect int64 vs int32 edge_index + zero histogram + zero scan state.
__global__ void detect_zero_kernel(const void* ei) {
    int i = blockIdx.x * blockDim.x + threadIdx.x;
    if (i < N_NODES) g_cnt[i] = 0;
    if (i < NB) g_state[i] = 0;       // replay-safe re-init
    if (i == 0) {
        const long long* p = (const long long*)ei;
        int ok = 1;
        for (int k = 0; k < 256; k++) {
            long long v = p[k];
            if (v < 0 || v >= N_NODES) { ok = 0; break; }
        }
        g_is64 = ok;
    }
}

// Histogram of dst — 4 edges per thread for atomic ILP
__global__ void hist_kernel(const void* ei) {
    int is64 = g_is64;
    int base = (blockIdx.x * blockDim.x + threadIdx.x) * 4;
    if (base + 4 <= N_EDGES) {
        int d0, d1, d2, d3;
        if (!is64) {
            int4 dv = *(const int4*)((const int*)ei + N_EDGES + base);
            d0 = dv.x; d1 = dv.y; d2 = dv.z; d3 = dv.w;
        } else {
            const long long* p = (const long long*)ei + N_EDGES + base;
            d0 = (int)p[0]; d1 = (int)p[1]; d2 = (int)p[2]; d3 = (int)p[3];
        }
        atomicAdd(&g_cnt[d0], 1);
        atomicAdd(&g_cnt[d1], 1);
        atomicAdd(&g_cnt[d2], 1);
        atomicAdd(&g_cnt[d3], 1);
    } else {
        for (int e = base; e < N_EDGES; e++)
            atomicAdd(&g_cnt[edge_idx(ei, N_EDGES + e, is64)], 1);
    }
}

// ---------------------------------------------------------------------------
// Single-pass scan (WARP-PARALLEL decoupled lookback) + dinv + fill-cursor
// + fused ys32 = dinv*x scaling. Block b handles nodes [b*256, b*256+256).
// ---------------------------------------------------------------------------
__global__ void __launch_bounds__(SCAN_B) scan_fused_kernel(
    const float* __restrict__ x) {
    __shared__ int sh[SCAN_B];
    __shared__ int s_base;
    __shared__ float sdv[SCAN_B];
    int t = threadIdx.x, b = blockIdx.x;
    int i = b * SCAN_B + t;
    int c = (i < N_NODES) ? g_cnt[i] : 0;

    // inclusive Hillis-Steele scan
    sh[t] = c;
    __syncthreads();
#pragma unroll
    for (int off = 1; off < SCAN_B; off <<= 1) {
        int u = (t >= off) ? sh[t - off] : 0;
        __syncthreads();
        sh[t] += u;
        __syncthreads();
    }
    int incl = sh[t];
    int blockTotal = sh[SCAN_B - 1];

    if (t == 0) {
        if (b == 0) {
            atomicExch(&g_state[0], blockTotal | FLAG_PRE);
            s_base = 0;
        } else {
            atomicExch(&g_state[b], blockTotal | FLAG_AGG);
        }
    }
    // warp-parallel lookback: 32 predecessors inspected per round
    if (b > 0 && t < 32) {
        int base = 0;
        int j = b - 1 - t;
        for (;;) {
            int v;
            if (j >= 0) {
                do { v = atomicAdd(&g_state[j], 0); } while ((v & ~VAL_MASK) == 0);
            } else {
                v = FLAG_PRE;   // virtual predecessor with prefix 0
            }
            unsigned preMask = __ballot_sync(0xffffffffu, (v & FLAG_PRE) != 0);
            int firstPre = preMask ? (__ffs(preMask) - 1) : 32;
            int contrib = (t <= firstPre) ? (v & VAL_MASK) : 0;
#pragma unroll
            for (int o = 16; o > 0; o >>= 1)
                contrib += __shfl_xor_sync(0xffffffffu, contrib, o);
            base += contrib;
            if (preMask) break;
            j -= 32;
        }
        if (t == 0) {
            atomicExch(&g_state[b], (base + blockTotal) | FLAG_PRE);
            s_base = base;
        }
    }
    float dv = rsqrtf((float)(c + 1));   // deg incl. self-loop
    sdv[t] = dv;
    __syncthreads();

    int r = s_base + incl - c;           // exclusive global prefix
    if (i < N_NODES) {
        g_row[i] = r;
        g_cnt[i] = r;                     // fill cursor
        g_dinv[i] = dv;
    }
    if (i == 0) g_row[N_NODES] = N_EDGES;

    // fused scale0: ys32 = dinv * x for this block's 256 nodes (8 float4/node)
    const float4* x4 = (const float4*)x;
    float4* y4 = (float4*)g_ys32;
    int node0 = b * SCAN_B;
    for (int k = t; k < SCAN_B * 8; k += SCAN_B) {
        int ln = k >> 3;
        int node = node0 + ln;
        if (node < N_NODES) {
            float4 v = x4[node * 8 + (k & 7)];
            float d = sdv[ln];
            y4[node * 8 + (k & 7)] = make_float4(d * v.x, d * v.y, d * v.z, d * v.w);
        }
    }
}

// Bucket fill — 4 edges per thread for atomic ILP
__global__ void fill_kernel(const void* ei) {
    int is64 = g_is64;
    int base = (blockIdx.x * blockDim.x + threadIdx.x) * 4;
    if (base + 4 <= N_EDGES) {
        int s0, s1, s2, s3, d0, d1, d2, d3;
        if (!is64) {
            int4 sv = *(const int4*)((const int*)ei + base);
            int4 dv = *(const int4*)((const int*)ei + N_EDGES + base);
            s0 = sv.x; s1 = sv.y; s2 = sv.z; s3 = sv.w;
            d0 = dv.x; d1 = dv.y; d2 = dv.z; d3 = dv.w;
        } else {
            const long long* ps = (const long long*)ei + base;
            const long long* pd = (const long long*)ei + N_EDGES + base;
            s0 = (int)ps[0]; s1 = (int)ps[1]; s2 = (int)ps[2]; s3 = (int)ps[3];
            d0 = (int)pd[0]; d1 = (int)pd[1]; d2 = (int)pd[2]; d3 = (int)pd[3];
        }
        int p0 = atomicAdd(&g_cnt[d0], 1);
        int p1 = atomicAdd(&g_cnt[d1], 1);
        int p2 = atomicAdd(&g_cnt[d2], 1);
        int p3 = atomicAdd(&g_cnt[d3], 1);
        g_srcs[p0] = s0; g_srcs[p1] = s1; g_srcs[p2] = s2; g_srcs[p3] = s3;
    } else {
        for (int e = base; e < N_EDGES; e++) {
            int s = edge_idx(ei, e, is64);
            int d = edge_idx(ei, N_EDGES + e, is64);
            int pos = atomicAdd(&g_cnt[d], 1);
            g_srcs[pos] = s;
        }
    }
}

// ---------------------------------------------------------------------------
// Fused pull + GEMM kernels. 256 threads = 8 warps; one warp per node.
// Gathers are float4 per lane with sub-warp row groups:
//   pull1: quarter-warp per 32-dim row -> 4 rows per LDG.128, x2 unroll = 8 MLP
//   pull2/3: half-warp per 64-dim row  -> 2 rows per LDG.128, x2 unroll = 4 MLP
// Cross-group combine via shfl_xor.
// ---------------------------------------------------------------------------

// Layer 1: a[32] = dinv*(Σ ys32[src] + ys32[n]); bufA = dinv*relu(a@W1 + b1)
__global__ void __launch_bounds__(256) pull1_kernel(
    const float* __restrict__ W1, const float* __restrict__ b1) {
    __shared__ float sW[32 * 64];
    __shared__ float sb[64];
    __shared__ float4 sa[8][8];   // 8 warps x 32 floats
    int tid = threadIdx.x;
    for (int i = tid; i < 32 * 64; i += 256) sW[i] = W1[i];
    if (tid < 64) sb[tid] = b1[tid];
    __syncthreads();

    int w = tid >> 5, lane = tid & 31;
    int grp = lane >> 3;      // 0..3 — which row this lane helps gather
    int sub = lane & 7;       // float4 slot within the 32-dim row
    const float4* ys4 = (const float4*)g_ys32;
    for (int n = blockIdx.x * 8 + w; n < N_NODES; n += gridDim.x * 8) {
        int e = g_row[n], end = g_row[n + 1];
        float4 acc0 = (grp == 0) ? ys4[n * 8 + sub] : make_float4(0.f, 0.f, 0.f, 0.f);
        float4 acc1 = make_float4(0.f, 0.f, 0.f, 0.f);
        for (; e + 8 <= end; e += 8) {
            int s0 = g_srcs[e + grp];
            int s1 = g_srcs[e + 4 + grp];
            float4 v0 = ys4[s0 * 8 + sub];
            float4 v1 = ys4[s1 * 8 + sub];
            acc0.x += v0.x; acc0.y += v0.y; acc0.z += v0.z; acc0.w += v0.w;
            acc1.x += v1.x; acc1.y += v1.y; acc1.z += v1.z; acc1.w += v1.w;
        }
        for (; e < end; e += 4) {
            int idx = e + grp;
            int ii = (idx < end) ? idx : e;   // clamp to valid slot
            float4 v = ys4[g_srcs[ii] * 8 + sub];
            if (idx < end) {
                acc0.x += v.x; acc0.y += v.y; acc0.z += v.z; acc0.w += v.w;
            }
        }
        float4 a = make_float4(acc0.x + acc1.x, acc0.y + acc1.y,
                               acc0.z + acc1.z, acc0.w + acc1.w);
        a.x += __shfl_xor_sync(0xffffffffu, a.x, 8);
        a.y += __shfl_xor_sync(0xffffffffu, a.y, 8);
        a.z += __shfl_xor_sync(0xffffffffu, a.z, 8);
        a.w += __shfl_xor_sync(0xffffffffu, a.w, 8);
        a.x += __shfl_xor_sync(0xffffffffu, a.x, 16);
        a.y += __shfl_xor_sync(0xffffffffu, a.y, 16);
        a.z += __shfl_xor_sync(0xffffffffu, a.z, 16);
        a.w += __shfl_xor_sync(0xffffffffu, a.w, 16);
        float dv = g_dinv[n];
        if (grp == 0)
            sa[w][sub] = make_float4(dv * a.x, dv * a.y, dv * a.z, dv * a.w);
        __syncwarp();
        // GEMM: this lane computes outputs 2*lane, 2*lane+1
        float s0 = sb[2 * lane], s1 = sb[2 * lane + 1];
#pragma unroll
        for (int k4 = 0; k4 < 8; k4++) {
            float4 aa = sa[w][k4];
            float2 r0 = *(const float2*)&sW[(4 * k4 + 0) * 64 + 2 * lane];
            float2 r1 = *(const float2*)&sW[(4 * k4 + 1) * 64 + 2 * lane];
            float2 r2 = *(const float2*)&sW[(4 * k4 + 2) * 64 + 2 * lane];
            float2 r3 = *(const float2*)&sW[(4 * k4 + 3) * 64 + 2 * lane];
            s0 = fmaf(aa.x, r0.x, s0); s1 = fmaf(aa.x, r0.y, s1);
            s0 = fmaf(aa.y, r1.x, s0); s1 = fmaf(aa.y, r1.y, s1);
            s0 = fmaf(aa.z, r2.x, s0); s1 = fmaf(aa.z, r2.y, s1);
            s0 = fmaf(aa.w, r3.x, s0); s1 = fmaf(aa.w, r3.y, s1);
        }
        float2 o = make_float2(dv * fmaxf(s0, 0.f), dv * fmaxf(s1, 0.f));
        ((float2*)g_bufA)[n * 32 + lane] = o;
        __syncwarp();   // everyone done with sa[w] before next iteration
    }
}

// 64-dim pull: half-warp per row, float4 lanes, x2 unroll. Returns combined
// (pre-dinv) sum replicated across the warp.
__device__ __forceinline__ float4 pull64v(const float4* __restrict__ in4,
                                          int n, int half, int sub) {
    int e = g_row[n], end = g_row[n + 1];
    float4 acc0 = (half == 0) ? in4[n * 16 + sub] : make_float4(0.f, 0.f, 0.f, 0.f);
    float4 acc1 = make_float4(0.f, 0.f, 0.f, 0.f);
    for (; e + 4 <= end; e += 4) {
        int s0 = g_srcs[e + half];
        int s1 = g_srcs[e + 2 + half];
        float4 v0 = in4[s0 * 16 + sub];
        float4 v1 = in4[s1 * 16 + sub];
        acc0.x += v0.x; acc0.y += v0.y; acc0.z += v0.z; acc0.w += v0.w;
        acc1.x += v1.x; acc1.y += v1.y; acc1.z += v1.z; acc1.w += v1.w;
    }
    for (; e < end; e += 2) {
        int idx = e + half;
        int ii = (idx < end) ? idx : e;
        float4 v = in4[g_srcs[ii] * 16 + sub];
        if (idx < end) {
            acc0.x += v.x; acc0.y += v.y; acc0.z += v.z; acc0.w += v.w;
        }
    }
    float4 a = make_float4(acc0.x + acc1.x, acc0.y + acc1.y,
                           acc0.z + acc1.z, acc0.w + acc1.w);
    a.x += __shfl_xor_sync(0xffffffffu, a.x, 16);
    a.y += __shfl_xor_sync(0xffffffffu, a.y, 16);
    a.z += __shfl_xor_sync(0xffffffffu, a.z, 16);
    a.w += __shfl_xor_sync(0xffffffffu, a.w, 16);
    return a;
}

// Layer 2: pull 64-dim from bufA, GEMM 64x64, bufB = dinv*relu(.)
__global__ void __launch_bounds__(256) pull2_kernel(
    const float* __restrict__ W2, const float* __restrict__ b2) {
    __shared__ float sW[64 * 64];
    __shared__ float sb[64];
    __shared__ float4 sa[8][16];  // 8 warps x 64 floats
    int tid = threadIdx.x;
    for (int i = tid; i < 64 * 64; i += 256) sW[i] = W2[i];
    if (tid < 64) sb[tid] = b2[tid];
    __syncthreads();

    int w = tid >> 5, lane = tid & 31;
    int half = lane >> 4, sub = lane & 15;
    const float4* in4 = (const float4*)g_bufA;
    for (int n = blockIdx.x * 8 + w; n < N_NODES; n += gridDim.x * 8) {
        float4 a = pull64v(in4, n, half, sub);
        float dv = g_dinv[n];
        if (half == 0)
            sa[w][sub] = make_float4(dv * a.x, dv * a.y, dv * a.z, dv * a.w);
        __syncwarp();
        float s0 = sb[2 * lane], s1 = sb[2 * lane + 1];
#pragma unroll
        for (int k4 = 0; k4 < 16; k4++) {
            float4 aa = sa[w][k4];
            float2 r0 = *(const float2*)&sW[(4 * k4 + 0) * 64 + 2 * lane];
            float2 r1 = *(const float2*)&sW[(4 * k4 + 1) * 64 + 2 * lane];
            float2 r2 = *(const float2*)&sW[(4 * k4 + 2) * 64 + 2 * lane];
            float2 r3 = *(const float2*)&sW[(4 * k4 + 3) * 64 + 2 * lane];
            s0 = fmaf(aa.x, r0.x, s0); s1 = fmaf(aa.x, r0.y, s1);
            s0 = fmaf(aa.y, r1.x, s0); s1 = fmaf(aa.y, r1.y, s1);
            s0 = fmaf(aa.z, r2.x, s0); s1 = fmaf(aa.z, r2.y, s1);
            s0 = fmaf(aa.w, r3.x, s0); s1 = fmaf(aa.w, r3.y, s1);
        }
        float2 o = make_float2(dv * fmaxf(s0, 0.f), dv * fmaxf(s1, 0.f));
        ((float2*)g_bufB)[n * 32 + lane] = o;
        __syncwarp();
    }
}

// Heads: pull 64-dim from bufB (ONE aggregation for both heads),
// mu = a@W_mu+b_mu, lv = a@W_lv+b_lv, z = mu + exp(0.5 lv)*eps.
// Output layout: [z | mu | logvar].
__global__ void __launch_bounds__(256) pull3_kernel(
    const float* __restrict__ W_mu, const float* __restrict__ b_mu,
    const float* __restrict__ W_lv, const float* __restrict__ b_lv,
    const float* __restrict__ eps, float* __restrict__ out) {
    __shared__ float2 sWml[64 * 32];   // interleaved {Wmu, Wlv}
    __shared__ float sbm[32], sbl[32];
    __shared__ float4 sa[8][16];
    int tid = threadIdx.x;
    for (int i = tid; i < 64 * 32; i += 256)
        sWml[i] = make_float2(W_mu[i], W_lv[i]);
    if (tid < 32) { sbm[tid] = b_mu[tid]; sbl[tid] = b_lv[tid]; }
    __syncthreads();

    int w = tid >> 5, lane = tid & 31;
    int half = lane >> 4, sub = lane & 15;
    const float4* in4 = (const float4*)g_bufB;
    for (int n = blockIdx.x * 8 + w; n < N_NODES; n += gridDim.x * 8) {
        float4 a = pull64v(in4, n, half, sub);
        float dv = g_dinv[n];
        if (half == 0)
            sa[w][sub] = make_float4(dv * a.x, dv * a.y, dv * a.z, dv * a.w);
        __syncwarp();
        float mu = sbm[lane], lv = sbl[lane];
#pragma unroll
        for (int k4 = 0; k4 < 16; k4++) {
            float4 aa = sa[w][k4];
            float2 m0 = sWml[(4 * k4 + 0) * 32 + lane];
            float2 m1 = sWml[(4 * k4 + 1) * 32 + lane];
            float2 m2 = sWml[(4 * k4 + 2) * 32 + lane];
            float2 m3 = sWml[(4 * k4 + 3) * 32 + lane];
            mu = fmaf(aa.x, m0.x, mu); lv = fmaf(aa.x, m0.y, lv);
            mu = fmaf(aa.y, m1.x, mu); lv = fmaf(aa.y, m1.y, lv);
            mu = fmaf(aa.z, m2.x, mu); lv = fmaf(aa.z, m2.y, lv);
            mu = fmaf(aa.w, m3.x, mu); lv = fmaf(aa.w, m3.y, lv);
        }
        float z = fmaf(expf(0.5f * lv), eps[n * 32 + lane], mu);
        int o = n * 32 + lane;
        out[o] = z;
        out[NZ + o] = mu;
        out[2 * NZ + o] = lv;
        __syncwarp();
    }
}

// ---------------------------------------------------------------------------
extern "C" void kernel_launch(void* const* d_in, const int* in_sizes, int n_in,
                              void* d_out, int out_size) {
    const float* x    = (const float*)d_in[0];
    const void*  ei   = d_in[1];
    const float* W1   = (const float*)d_in[2];
    const float* b1   = (const float*)d_in[3];
    const float* W2   = (const float*)d_in[4];
    const float* b2   = (const float*)d_in[5];
    const float* W_mu = (const float*)d_in[6];
    const float* b_mu = (const float*)d_in[7];
    const float* W_lv = (const float*)d_in[8];
    const float* b_lv = (const float*)d_in[9];
    const float* eps  = (const float*)d_in[10];
    float* out = (float*)d_out;

    const int TB = 256;
    auto grid = [](long long n, int tb) { return (int)((n + tb - 1) / tb); };
    const int PG = 1184;   // persistent pull blocks

    detect_zero_kernel<<<grid(N_NODES, TB), TB>>>(ei);
    hist_kernel<<<grid((N_EDGES + 3) / 4, TB), TB>>>(ei);
    scan_fused_kernel<<<NB, SCAN_B>>>(x);     // scan + dinv + cursor + scale0
    fill_kernel<<<grid((N_EDGES + 3) / 4, TB), TB>>>(ei);

    pull1_kernel<<<PG, 256>>>(W1, b1);
    pull2_kernel<<<PG, 256>>>(W2, b2);
    pull3_kernel<<<PG, 256>>>(W_mu, b_mu, W_lv, b_lv, eps, out);
}